// round 4
// baseline (speedup 1.0000x reference)
#include <cuda_runtime.h>
#include <cuda_bf16.h>
#include <cmath>
#include <complex>

// ----------------------------------------------------------------------------
// Constants / layout
// ----------------------------------------------------------------------------
#define NF       196
#define STRIDE   197      // odd -> conflict-free
#define EPB      64       // edges per block
#define NTHREADS 256      // 8 warps: 4 parts x 2 edge-groups
#define DSTRIDE  35       // odd stride for D buffer (9 + 25 = 34 floats used)
#define SMEM_FLOATS (EPB * STRIDE + EPB * DSTRIDE)
#define SMEM_BYTES  (SMEM_FLOATS * 4)

struct Params {
    float cg[1225];  // concatenated per-pair CG, layout (a*L2+b)*R + r
    float c5[45];    // sqrt(5) * wigner_3j(1,1,2), layout (m1*3+m2)*5 + M
};

// pair table: l1, l2, nch, feature offset, cg offset
// sizes: ss 9, sp 18, sd 15, ps 18, pp 36, pd 30, ds 15, dp 30, dd 25 = 196
// cg sizes (R^2): 1, 9, 25, 9, 81, 225, 25, 225, 625 = 1225

// ----------------------------------------------------------------------------
// Host-side CG computation: exact float64 mirror of the numpy reference.
// ----------------------------------------------------------------------------
typedef std::complex<double> cd;

static double hfact(int n) { double r = 1.0; for (int i = 2; i <= n; i++) r *= i; return r; }

static double su2_cg(int j1, int j2, int j3, int m1, int m2, int m3) {
    if (m3 != m1 + m2) return 0.0;
    int vmin = -j1 + j2 + m3;
    if (-j1 + m1 > vmin) vmin = -j1 + m1;
    if (0 > vmin) vmin = 0;
    int vmax = j2 + j3 + m1;
    if (j3 - j1 + j2 < vmax) vmax = j3 - j1 + j2;
    if (j3 + m3 < vmax) vmax = j3 + m3;
    double C = std::sqrt((2.0 * j3 + 1.0) * hfact(j3 + j1 - j2) * hfact(j3 - j1 + j2)
                         * hfact(j1 + j2 - j3) * hfact(j3 + m3) * hfact(j3 - m3)
                         / (hfact(j1 + j2 + j3 + 1) * hfact(j1 - m1) * hfact(j1 + m1)
                            * hfact(j2 - m2) * hfact(j2 + m2)));
    double S = 0.0;
    for (int v = vmin; v <= vmax; v++) {
        double sg = ((v + j2 + m2) & 1) ? -1.0 : 1.0;
        S += sg * hfact(j2 + j3 + m1 - v) * hfact(j1 - m1 + v)
             / (hfact(v) * hfact(j3 - j1 + j2 - v) * hfact(j3 + m3 - v)
                * hfact(v + j1 - j2 - m3));
    }
    return C * S;
}

static void change_basis(int l, cd* Q) {  // Q[(2l+1)^2], row-major
    int L = 2 * l + 1;
    for (int i = 0; i < L * L; i++) Q[i] = cd(0, 0);
    double is2 = 1.0 / std::sqrt(2.0);
    for (int m = -l; m < 0; m++) {
        Q[(l + m) * L + (l - m)] = cd(is2, 0);
        Q[(l + m) * L + (l + m)] = cd(0, -is2);
    }
    Q[l * L + l] = cd(1, 0);
    for (int m = 1; m <= l; m++) {
        double sg = (m & 1) ? -1.0 : 1.0;
        Q[(l + m) * L + (l + m)] = cd(sg * is2, 0);
        Q[(l + m) * L + (l - m)] = cd(0, sg * is2);
    }
    cd ph(1, 0);
    const cd mi(0, -1);
    for (int k = 0; k < l; k++) ph *= mi;   // (-i)^l
    for (int i = 0; i < L * L; i++) Q[i] *= ph;
}

static void wigner3j(int l1, int l2, int l3, double* out) {
    int L1 = 2 * l1 + 1, L2 = 2 * l2 + 1, L3 = 2 * l3 + 1;
    cd C[225];
    for (int i = 0; i < L1; i++)
        for (int k = 0; k < L2; k++)
            for (int n = 0; n < L3; n++)
                C[(i * L2 + k) * L3 + n] = cd(su2_cg(l1, l2, l3, i - l1, k - l2, n - l3), 0.0);
    cd Q1[25], Q2[25], Q3[81];
    change_basis(l1, Q1); change_basis(l2, Q2); change_basis(l3, Q3);
    double nrm = 0.0;
    for (int j = 0; j < L1; j++)
        for (int l = 0; l < L2; l++)
            for (int m = 0; m < L3; m++) {
                cd s(0, 0);
                for (int i = 0; i < L1; i++)
                    for (int k = 0; k < L2; k++)
                        for (int n = 0; n < L3; n++)
                            s += Q1[i * L1 + j] * Q2[k * L2 + l]
                               * std::conj(Q3[n * L3 + m]) * C[(i * L2 + k) * L3 + n];
                double v = s.real();
                out[(j * L2 + l) * L3 + m] = v;
                nrm += v * v;
            }
    nrm = std::sqrt(nrm);
    for (int t = 0; t < L1 * L2 * L3; t++) out[t] /= nrm;
}

static void build_params(Params& P) {
    static const int l1s[9]   = {0, 0, 0, 1, 1, 1, 2, 2, 2};
    static const int l2s[9]   = {0, 1, 2, 0, 1, 2, 0, 1, 2};
    static const int cgoff[9] = {0, 1, 10, 35, 44, 125, 350, 375, 600};
    for (int p = 0; p < 9; p++) {
        int l1 = l1s[p], l2 = l2s[p];
        int L1 = 2 * l1 + 1, L2 = 2 * l2 + 1, R = L1 * L2;
        double cg[625];
        int lmin = (l1 > l2) ? (l1 - l2) : (l2 - l1);
        int rof = 0;
        for (int l3 = lmin; l3 <= l1 + l2; l3++) {
            double w[225];
            wigner3j(l1, l2, l3, w);
            int L3 = 2 * l3 + 1;
            double sc = std::sqrt(2.0 * l3 + 1.0);
            for (int a = 0; a < L1; a++)
                for (int b = 0; b < L2; b++)
                    for (int nn = 0; nn < L3; nn++)
                        cg[(a * L2 + b) * R + rof + nn] = w[(a * L2 + b) * L3 + nn] * sc;
            rof += L3;
        }
        for (int t = 0; t < R * R; t++) P.cg[cgoff[p] + t] = (float)cg[t];
    }
    double w[45];
    wigner3j(1, 1, 2, w);
    double s5 = std::sqrt(5.0);
    for (int t = 0; t < 45; t++) P.c5[t] = (float)(w[t] * s5);
}

// ----------------------------------------------------------------------------
// Device: streaming pair transform. row points into smem; rme is streamed
// (no register copy), output written back in place after each channel.
// ----------------------------------------------------------------------------
template <int L1, int L2, int NCH>
__device__ __forceinline__ void do_pair(float* __restrict__ row,
                                        const float* __restrict__ cg,
                                        const float* __restrict__ Dl,
                                        const float* __restrict__ Dr) {
    constexpr int R = L1 * L2;
#pragma unroll
    for (int q = 0; q < NCH; ++q) {
        float Hz[R];
#pragma unroll
        for (int ab = 0; ab < R; ++ab) Hz[ab] = 0.f;
#pragma unroll
        for (int r = 0; r < R; ++r) {
            float x = row[q * R + r];          // LDS, conflict-free (stride 197)
#pragma unroll
            for (int ab = 0; ab < R; ++ab)
                Hz[ab] = fmaf(cg[ab * R + r], x, Hz[ab]);
        }
#pragma unroll
        for (int l = 0; l < L1; ++l) {
            float T[L2];
#pragma unroll
            for (int b = 0; b < L2; ++b) {
                float s = 0.f;
#pragma unroll
                for (int m = 0; m < L1; ++m)
                    s = fmaf(Dl[l * L1 + m], Hz[m * L2 + b], s);
                T[b] = s;
            }
#pragma unroll
            for (int k = 0; k < L2; ++k) {
                float s = 0.f;
#pragma unroll
                for (int o = 0; o < L2; ++o)
                    s = fmaf(T[o], Dr[k * L2 + o], s);
                row[q * R + l * L2 + k] = s;   // STS after this channel's reads
            }
        }
    }
}

__global__ void __launch_bounds__(NTHREADS, 2)
e3_kernel(const float* __restrict__ feat, const float* __restrict__ vec,
          float* __restrict__ out, int n, const __grid_constant__ Params P) {
    extern __shared__ float smem[];
    float* tile = smem;                        // EPB x STRIDE
    float* Dbuf = smem + EPB * STRIDE;         // EPB x DSTRIDE (D1: 0..8, D2: 9..33)

    const int tid = threadIdx.x;
    const int e0 = blockIdx.x * EPB;
    const int nvalid = min(EPB, n - e0);
    const int nf4 = nvalid * 49;               // 196 floats = 49 float4 per row

    // ---- issue vec loads early for the D-compute threads ----
    float vx = 0.f, vy = 0.f, vz = 0.f;
    if (tid < nvalid) {
        const int e = e0 + tid;
        vx = vec[3 * e + 0]; vy = vec[3 * e + 1]; vz = vec[3 * e + 2];
    }

    // ---- coalesced feature load -> smem tile ----
    const float4* g4 = reinterpret_cast<const float4*>(feat + (size_t)e0 * NF);
    for (int i = tid; i < nf4; i += NTHREADS) {
        float4 v = g4[i];
        int r = i / 49;
        int c = (i - r * 49) * 4;
        float* p = &tile[r * STRIDE + c];
        p[0] = v.x; p[1] = v.y; p[2] = v.z; p[3] = v.w;
    }

    // ---- threads 0..63: compute D1, D2 for their edge -> Dbuf ----
    if (tid < nvalid) {
        float inv = rsqrtf(fmaf(vx, vx, fmaf(vy, vy, vz * vz)));
        vx *= inv; vy *= inv; vz *= inv;
        float cb = fminf(1.f, fmaxf(-1.f, vy));
        float sb = sqrtf(fmaxf(0.f, 1.f - cb * cb));
        float rho2 = fmaf(vx, vx, vz * vz);
        float ca, sa;
        if (rho2 > 0.f) {
            float ir = rsqrtf(rho2);
            ca = vz * ir; sa = vx * ir;
        } else { ca = 1.f; sa = 0.f; }

        float D1m[9] = { ca,  sa * sb,  sa * cb,
                         0.f, cb,      -sb,
                        -sa,  ca * sb,  ca * cb };

        float* Drow = &Dbuf[tid * DSTRIDE];
#pragma unroll
        for (int i = 0; i < 9; ++i) Drow[i] = D1m[i];

        // D2 = C5^T (D1 (x) D1) C5
#pragma unroll
        for (int N = 0; N < 5; ++N) {
            float U[9];
#pragma unroll
            for (int m2 = 0; m2 < 3; ++m2)
#pragma unroll
                for (int n1 = 0; n1 < 3; ++n1) {
                    float s = 0.f;
#pragma unroll
                    for (int n2 = 0; n2 < 3; ++n2)
                        s = fmaf(D1m[m2 * 3 + n2], P.c5[(n1 * 3 + n2) * 5 + N], s);
                    U[m2 * 3 + n1] = s;
                }
            float E[9];
#pragma unroll
            for (int m1 = 0; m1 < 3; ++m1)
#pragma unroll
                for (int m2 = 0; m2 < 3; ++m2) {
                    float s = 0.f;
#pragma unroll
                    for (int n1 = 0; n1 < 3; ++n1)
                        s = fmaf(D1m[m1 * 3 + n1], U[m2 * 3 + n1], s);
                    E[m1 * 3 + m2] = s;
                }
#pragma unroll
            for (int M = 0; M < 5; ++M) {
                float s = 0.f;
#pragma unroll
                for (int mm = 0; mm < 9; ++mm)
                    s = fmaf(P.c5[mm * 5 + M], E[mm], s);
                Drow[9 + M * 5 + N] = s;
            }
        }
    }
    __syncthreads();

    // ---- warp-specialized compute: warp w -> part w%4, edge 32*(w/4)+lane ----
    {
        const int warp = tid >> 5;
        const int lane = tid & 31;
        const int part = warp & 3;
        const int e_loc = ((warp >> 2) << 5) + lane;
        if (e_loc < nvalid) {
            float* row = &tile[e_loc * STRIDE];
            const float* Drow = &Dbuf[e_loc * DSTRIDE];
            const float D0m[1] = {1.f};
            if (part == 0) {
                float D2m[25];
#pragma unroll
                for (int i = 0; i < 25; ++i) D2m[i] = Drow[9 + i];
                do_pair<5, 5, 1>(row + 171, P.cg + 600, D2m, D2m);   // d-d
            } else if (part == 1) {
                float D1m[9], D2m[25];
#pragma unroll
                for (int i = 0; i < 9; ++i)  D1m[i] = Drow[i];
#pragma unroll
                for (int i = 0; i < 25; ++i) D2m[i] = Drow[9 + i];
                do_pair<3, 5, 2>(row + 96, P.cg + 125, D1m, D2m);    // p-d
                do_pair<1, 5, 3>(row + 27, P.cg + 10,  D0m, D2m);    // s-d
            } else if (part == 2) {
                float D1m[9], D2m[25];
#pragma unroll
                for (int i = 0; i < 9; ++i)  D1m[i] = Drow[i];
#pragma unroll
                for (int i = 0; i < 25; ++i) D2m[i] = Drow[9 + i];
                do_pair<5, 3, 2>(row + 141, P.cg + 375, D2m, D1m);   // d-p
                do_pair<5, 1, 3>(row + 126, P.cg + 350, D2m, D0m);   // d-s
            } else {
                float D1m[9];
#pragma unroll
                for (int i = 0; i < 9; ++i) D1m[i] = Drow[i];
                do_pair<3, 3, 4>(row + 60, P.cg + 44, D1m, D1m);     // p-p
                do_pair<1, 3, 6>(row + 9,  P.cg + 1,  D0m, D1m);     // s-p
                do_pair<3, 1, 6>(row + 42, P.cg + 35, D1m, D0m);     // p-s
                do_pair<1, 1, 9>(row + 0,  P.cg + 0,  D0m, D0m);     // s-s
            }
        }
    }
    __syncthreads();

    // ---- coalesced store ----
    float4* o4 = reinterpret_cast<float4*>(out + (size_t)e0 * NF);
    for (int i = tid; i < nf4; i += NTHREADS) {
        int r = i / 49;
        int c = (i - r * 49) * 4;
        const float* p = &tile[r * STRIDE + c];
        o4[i] = make_float4(p[0], p[1], p[2], p[3]);
    }
}

// ----------------------------------------------------------------------------
// Launch
// ----------------------------------------------------------------------------
extern "C" void kernel_launch(void* const* d_in, const int* in_sizes, int n_in,
                              void* d_out, int out_size) {
    (void)n_in; (void)out_size;
    const float* feat = (const float*)d_in[0];
    const float* vec  = (const float*)d_in[1];
    float* out = (float*)d_out;
    const int n = in_sizes[0] / NF;

    Params P;
    build_params(P);

    cudaFuncSetAttribute(e3_kernel, cudaFuncAttributeMaxDynamicSharedMemorySize, SMEM_BYTES);
    int blocks = (n + EPB - 1) / EPB;
    e3_kernel<<<blocks, NTHREADS, SMEM_BYTES>>>(feat, vec, out, n, P);
}

// round 5
// speedup vs baseline: 1.5912x; 1.5912x over previous
#include <cuda_runtime.h>
#include <cuda_bf16.h>

// ----------------------------------------------------------------------------
// Constants / layout
// ----------------------------------------------------------------------------
#define NF       196
#define STRIDE   197      // odd -> conflict-free smem column access
#define EPB      128
#define NTHREADS 128
#define SMEM_BYTES (EPB * STRIDE * 4)

// pair table: l1, l2, nch, feature offset, cg offset
// sizes: ss 9, sp 18, sd 15, ps 18, pp 36, pd 30, ds 15, dp 30, dd 25 = 196
// cg sizes (R^2): 1, 9, 25, 9, 81, 225, 25, 225, 625 = 1225

// ----------------------------------------------------------------------------
// Compile-time CG computation: constexpr float64 mirror of the numpy reference.
// All coefficients become instruction immediates in device code (no LDC).
// ----------------------------------------------------------------------------
struct CD { double re, im; };
constexpr CD cadd(CD a, CD b) { return {a.re + b.re, a.im + b.im}; }
constexpr CD cmulc(CD a, CD b) { return {a.re * b.re - a.im * b.im, a.re * b.im + a.im * b.re}; }
constexpr CD cscale(CD a, double s) { return {a.re * s, a.im * s}; }
constexpr CD cconj(CD a) { return {a.re, -a.im}; }
constexpr bool ciszero(CD a) { return a.re == 0.0 && a.im == 0.0; }

constexpr double cfact(int n) { double r = 1.0; for (int i = 2; i <= n; i++) r *= i; return r; }

constexpr double csqrt_(double x) {
    if (x <= 0.0) return 0.0;
    double y = x > 1.0 ? x : 1.0;
    for (int i = 0; i < 80; i++) {
        double ny = 0.5 * (y + x / y);
        if (ny == y) break;
        y = ny;
    }
    return y;
}

constexpr double su2_cg_c(int j1, int j2, int j3, int m1, int m2, int m3) {
    if (m3 != m1 + m2) return 0.0;
    int vmin = -j1 + j2 + m3;
    if (-j1 + m1 > vmin) vmin = -j1 + m1;
    if (0 > vmin) vmin = 0;
    int vmax = j2 + j3 + m1;
    if (j3 - j1 + j2 < vmax) vmax = j3 - j1 + j2;
    if (j3 + m3 < vmax) vmax = j3 + m3;
    double C = csqrt_((2.0 * j3 + 1.0) * cfact(j3 + j1 - j2) * cfact(j3 - j1 + j2)
                      * cfact(j1 + j2 - j3) * cfact(j3 + m3) * cfact(j3 - m3)
                      / (cfact(j1 + j2 + j3 + 1) * cfact(j1 - m1) * cfact(j1 + m1)
                         * cfact(j2 - m2) * cfact(j2 + m2)));
    double S = 0.0;
    for (int v = vmin; v <= vmax; v++) {
        double sg = ((v + j2 + m2) & 1) ? -1.0 : 1.0;
        S += sg * cfact(j2 + j3 + m1 - v) * cfact(j1 - m1 + v)
             / (cfact(v) * cfact(j3 - j1 + j2 - v) * cfact(j3 + m3 - v)
                * cfact(v + j1 - j2 - m3));
    }
    return C * S;
}

struct QM { CD q[81]; };   // up to L=9 (l3=4)

constexpr QM change_basis_c(int l) {
    QM Q{};
    int L = 2 * l + 1;
    for (int i = 0; i < L * L; i++) Q.q[i] = CD{0, 0};
    double is2 = 1.0 / csqrt_(2.0);
    for (int m = -l; m < 0; m++) {
        Q.q[(l + m) * L + (l - m)] = CD{is2, 0};
        Q.q[(l + m) * L + (l + m)] = CD{0, -is2};
    }
    Q.q[l * L + l] = CD{1, 0};
    for (int m = 1; m <= l; m++) {
        double sg = (m & 1) ? -1.0 : 1.0;
        Q.q[(l + m) * L + (l + m)] = CD{sg * is2, 0};
        Q.q[(l + m) * L + (l - m)] = CD{0, sg * is2};
    }
    CD ph{1, 0};
    for (int k = 0; k < l; k++) ph = cmulc(ph, CD{0, -1});   // (-i)^l
    for (int i = 0; i < L * L; i++) Q.q[i] = cmulc(Q.q[i], ph);
    return Q;
}

struct W3 { double w[225]; };

constexpr W3 wigner3j_c(int l1, int l2, int l3) {
    int L1 = 2 * l1 + 1, L2 = 2 * l2 + 1, L3 = 2 * l3 + 1;
    QM Q1 = change_basis_c(l1), Q2 = change_basis_c(l2), Q3 = change_basis_c(l3);
    CD acc[225]{};
    for (int t = 0; t < 225; t++) acc[t] = CD{0, 0};
    for (int i = 0; i < L1; i++)
        for (int k = 0; k < L2; k++)
            for (int n = 0; n < L3; n++) {
                double c = su2_cg_c(l1, l2, l3, i - l1, k - l2, n - l3);
                if (c == 0.0) continue;
                for (int j = 0; j < L1; j++) {
                    CD q1 = Q1.q[i * L1 + j];
                    if (ciszero(q1)) continue;
                    for (int l = 0; l < L2; l++) {
                        CD q2 = Q2.q[k * L2 + l];
                        if (ciszero(q2)) continue;
                        CD q12 = cmulc(q1, q2);
                        for (int m = 0; m < L3; m++) {
                            CD q3 = Q3.q[n * L3 + m];
                            if (ciszero(q3)) continue;
                            CD t = cmulc(q12, cconj(q3));
                            int o = (j * L2 + l) * L3 + m;
                            acc[o] = cadd(acc[o], cscale(t, c));
                        }
                    }
                }
            }
    W3 out{};
    double nrm = 0.0;
    for (int t = 0; t < L1 * L2 * L3; t++) { out.w[t] = acc[t].re; nrm += out.w[t] * out.w[t]; }
    nrm = csqrt_(nrm);
    for (int t = 0; t < L1 * L2 * L3; t++) out.w[t] /= nrm;
    return out;
}

struct CGTab { float cg[1225]; float c5[45]; };

constexpr CGTab build_cg_c() {
    CGTab P{};
    const int l1s[9]   = {0, 0, 0, 1, 1, 1, 2, 2, 2};
    const int l2s[9]   = {0, 1, 2, 0, 1, 2, 0, 1, 2};
    const int cgoff[9] = {0, 1, 10, 35, 44, 125, 350, 375, 600};
    for (int p = 0; p < 9; p++) {
        int l1 = l1s[p], l2 = l2s[p];
        int L1 = 2 * l1 + 1, L2 = 2 * l2 + 1, R = L1 * L2;
        int lmin = (l1 > l2) ? (l1 - l2) : (l2 - l1);
        int rof = 0;
        for (int l3 = lmin; l3 <= l1 + l2; l3++) {
            W3 w = wigner3j_c(l1, l2, l3);
            int L3 = 2 * l3 + 1;
            double sc = csqrt_(2.0 * l3 + 1.0);
            for (int a = 0; a < L1; a++)
                for (int b = 0; b < L2; b++)
                    for (int nn = 0; nn < L3; nn++)
                        P.cg[cgoff[p] + (a * L2 + b) * R + rof + nn] =
                            (float)(w.w[(a * L2 + b) * L3 + nn] * sc);
            rof += L3;
        }
    }
    W3 w = wigner3j_c(1, 1, 2);
    double s5 = csqrt_(5.0);
    for (int t = 0; t < 45; t++) P.c5[t] = (float)(w.w[t] * s5);
    return P;
}

constexpr CGTab CGH = build_cg_c();

// Scalar constexpr carriers: fold to immediates in device code (no odr-use).
template <int I> struct CGC { static constexpr float v = CGH.cg[I]; };
template <int I> struct C5C { static constexpr float v = CGH.c5[I]; };

// ----------------------------------------------------------------------------
// Index-sequence machinery (self-contained, device-safe)
// ----------------------------------------------------------------------------
template <int... Is> struct iseq {};
template <int N, int... Is> struct mkseq_ : mkseq_<N - 1, N - 1, Is...> {};
template <int... Is> struct mkseq_<0, Is...> { using type = iseq<Is...>; };
template <int N> using mkseq = typename mkseq_<N>::type;

template <int IDX>
__device__ __forceinline__ float cgfma(float x, float s) {
    constexpr float c = CGC<IDX>::v;
    if constexpr (c == 0.0f) return s;
    else return fmaf(c, x, s);            // FFMA-imm form, rt=1
}
template <int IDX>
__device__ __forceinline__ float c5fma(float x, float s) {
    constexpr float c = C5C<IDX>::v;
    if constexpr (c == 0.0f) return s;
    else return fmaf(c, x, s);
}

template <int BASE, int... Rs>
__device__ __forceinline__ float cgdot(const float* __restrict__ x, iseq<Rs...>) {
    float s = 0.f;
    ((s = cgfma<BASE + Rs>(x[Rs], s)), ...);
    return s;
}
template <int CGOFF, int R, int... ABs>
__device__ __forceinline__ void cgall(const float* __restrict__ x, float* __restrict__ Hz,
                                      iseq<ABs...>) {
    ((Hz[ABs] = cgdot<CGOFF + ABs * R>(x, mkseq<R>{})), ...);
}

// ----------------------------------------------------------------------------
// Pair transform: CG (immediates) then Dl * Hz * Dr^T, in-place on smem row.
// ----------------------------------------------------------------------------
template <int L1, int L2, int NCH, int CGOFF>
__device__ __forceinline__ void do_pair(float* __restrict__ row,
                                        const float* __restrict__ Dl,
                                        const float* __restrict__ Dr) {
    constexpr int R = L1 * L2;
#pragma unroll
    for (int q = 0; q < NCH; ++q) {
        float x[R];
#pragma unroll
        for (int r = 0; r < R; ++r) x[r] = row[q * R + r];
        float Hz[R];
        cgall<CGOFF, R>(x, Hz, mkseq<R>{});
#pragma unroll
        for (int l = 0; l < L1; ++l) {
            float T[L2];
#pragma unroll
            for (int b = 0; b < L2; ++b) {
                if constexpr (L1 == 1) {
                    T[b] = Hz[b];
                } else {
                    float s = 0.f;
#pragma unroll
                    for (int m = 0; m < L1; ++m)
                        s = fmaf(Dl[l * L1 + m], Hz[m * L2 + b], s);
                    T[b] = s;
                }
            }
#pragma unroll
            for (int k = 0; k < L2; ++k) {
                if constexpr (L2 == 1) {
                    row[q * R + l * L2 + k] = T[0];
                } else {
                    float s = 0.f;
#pragma unroll
                    for (int o = 0; o < L2; ++o)
                        s = fmaf(T[o], Dr[k * L2 + o], s);
                    row[q * R + l * L2 + k] = s;
                }
            }
        }
    }
}

// ----------------------------------------------------------------------------
// D2 = C5^T (D1 (x) D1) C5, all C5 coefficients as immediates.
// ----------------------------------------------------------------------------
template <int N, int N1>
__device__ __forceinline__ float u_ent(const float* __restrict__ d1row) {
    float s = 0.f;
    s = c5fma<(N1 * 3 + 0) * 5 + N>(d1row[0], s);
    s = c5fma<(N1 * 3 + 1) * 5 + N>(d1row[1], s);
    s = c5fma<(N1 * 3 + 2) * 5 + N>(d1row[2], s);
    return s;
}
template <int M, int... MMs>
__device__ __forceinline__ float d2_ent(const float* __restrict__ E, iseq<MMs...>) {
    float s = 0.f;
    ((s = c5fma<MMs * 5 + M>(E[MMs], s)), ...);
    return s;
}
template <int N>
__device__ __forceinline__ void d2_col(const float* __restrict__ D1m, float* __restrict__ D2m) {
    float U[9];
#pragma unroll
    for (int m2 = 0; m2 < 3; ++m2) {
        U[m2 * 3 + 0] = u_ent<N, 0>(D1m + m2 * 3);
        U[m2 * 3 + 1] = u_ent<N, 1>(D1m + m2 * 3);
        U[m2 * 3 + 2] = u_ent<N, 2>(D1m + m2 * 3);
    }
    float E[9];
#pragma unroll
    for (int m1 = 0; m1 < 3; ++m1)
#pragma unroll
        for (int m2 = 0; m2 < 3; ++m2) {
            float s = 0.f;
#pragma unroll
            for (int n1 = 0; n1 < 3; ++n1)
                s = fmaf(D1m[m1 * 3 + n1], U[m2 * 3 + n1], s);
            E[m1 * 3 + m2] = s;
        }
    D2m[0 * 5 + N] = d2_ent<0>(E, mkseq<9>{});
    D2m[1 * 5 + N] = d2_ent<1>(E, mkseq<9>{});
    D2m[2 * 5 + N] = d2_ent<2>(E, mkseq<9>{});
    D2m[3 * 5 + N] = d2_ent<3>(E, mkseq<9>{});
    D2m[4 * 5 + N] = d2_ent<4>(E, mkseq<9>{});
}

// ----------------------------------------------------------------------------
// Kernel: one thread = one edge; coalesced load/store via smem tile.
// ----------------------------------------------------------------------------
__global__ void __launch_bounds__(NTHREADS, 2)
e3_kernel(const float* __restrict__ feat, const float* __restrict__ vec,
          float* __restrict__ out, int n) {
    extern __shared__ float tile[];
    const int tid = threadIdx.x;
    const int e0 = blockIdx.x * EPB;
    const int nvalid = min(EPB, n - e0);
    const int nf4 = nvalid * 49;   // 196 floats = 49 float4 per row

    // issue vec loads early
    float vx = 0.f, vy = 0.f, vz = 0.f;
    if (tid < nvalid) {
        const int e = e0 + tid;
        vx = vec[3 * e + 0]; vy = vec[3 * e + 1]; vz = vec[3 * e + 2];
    }

    // ---- coalesced feature load ----
    const float4* g4 = reinterpret_cast<const float4*>(feat + (size_t)e0 * NF);
    for (int i = tid; i < nf4; i += NTHREADS) {
        float4 v = g4[i];
        int r = i / 49;
        int c = (i - r * 49) * 4;
        float* p = &tile[r * STRIDE + c];
        p[0] = v.x; p[1] = v.y; p[2] = v.z; p[3] = v.w;
    }
    __syncthreads();

    // ---- compute: one thread per edge, in place ----
    if (tid < nvalid) {
        float inv = rsqrtf(fmaf(vx, vx, fmaf(vy, vy, vz * vz)));
        vx *= inv; vy *= inv; vz *= inv;
        float cb = fminf(1.f, fmaxf(-1.f, vy));
        float sb = sqrtf(fmaxf(0.f, 1.f - cb * cb));
        float rho2 = fmaf(vx, vx, vz * vz);
        float ca, sa;
        if (rho2 > 0.f) {
            float ir = rsqrtf(rho2);
            ca = vz * ir; sa = vx * ir;
        } else { ca = 1.f; sa = 0.f; }

        float D1m[9] = { ca,  sa * sb,  sa * cb,
                         0.f, cb,      -sb,
                        -sa,  ca * sb,  ca * cb };

        float D2m[25];
        d2_col<0>(D1m, D2m);
        d2_col<1>(D1m, D2m);
        d2_col<2>(D1m, D2m);
        d2_col<3>(D1m, D2m);
        d2_col<4>(D1m, D2m);

        float* row = &tile[tid * STRIDE];
        do_pair<1, 1, 9, 0  >(row + 0,   D1m, D1m);  // s-s (D unused)
        do_pair<1, 3, 6, 1  >(row + 9,   D1m, D1m);  // s-p
        do_pair<1, 5, 3, 10 >(row + 27,  D1m, D2m);  // s-d
        do_pair<3, 1, 6, 35 >(row + 42,  D1m, D1m);  // p-s
        do_pair<3, 3, 4, 44 >(row + 60,  D1m, D1m);  // p-p
        do_pair<3, 5, 2, 125>(row + 96,  D1m, D2m);  // p-d
        do_pair<5, 1, 3, 350>(row + 126, D2m, D1m);  // d-s
        do_pair<5, 3, 2, 375>(row + 141, D2m, D1m);  // d-p
        do_pair<5, 5, 1, 600>(row + 171, D2m, D2m);  // d-d
    }
    __syncthreads();

    // ---- coalesced store ----
    float4* o4 = reinterpret_cast<float4*>(out + (size_t)e0 * NF);
    for (int i = tid; i < nf4; i += NTHREADS) {
        int r = i / 49;
        int c = (i - r * 49) * 4;
        const float* p = &tile[r * STRIDE + c];
        o4[i] = make_float4(p[0], p[1], p[2], p[3]);
    }
}

// ----------------------------------------------------------------------------
// Launch
// ----------------------------------------------------------------------------
extern "C" void kernel_launch(void* const* d_in, const int* in_sizes, int n_in,
                              void* d_out, int out_size) {
    (void)n_in; (void)out_size;
    const float* feat = (const float*)d_in[0];
    const float* vec  = (const float*)d_in[1];
    float* out = (float*)d_out;
    const int n = in_sizes[0] / NF;

    cudaFuncSetAttribute(e3_kernel, cudaFuncAttributeMaxDynamicSharedMemorySize, SMEM_BYTES);
    int blocks = (n + EPB - 1) / EPB;
    e3_kernel<<<blocks, NTHREADS, SMEM_BYTES>>>(feat, vec, out, n);
}

// round 6
// speedup vs baseline: 1.9405x; 1.2195x over previous
#include <cuda_runtime.h>
#include <cuda_bf16.h>

// ----------------------------------------------------------------------------
// Constants / layout
// ----------------------------------------------------------------------------
#define NF       196
#define WA       96       // phase A: cols [0,96)   = ss,sp,sd,ps,pp
#define WB       100      // phase B: cols [96,196) = pd,ds,dp,dd
#define STRIDE   101      // odd -> conflict-free smem column access
#define EPB      128
#define NTHREADS 128
#define SMEM_BYTES (EPB * STRIDE * 4)

// pair table: l1, l2, nch, feature offset, cg offset
// sizes: ss 9, sp 18, sd 15, ps 18, pp 36 | pd 30, ds 15, dp 30, dd 25 = 196
// cg sizes (R^2): 1, 9, 25, 9, 81, 225, 25, 225, 625 = 1225

// ----------------------------------------------------------------------------
// Compile-time CG computation: constexpr float64 mirror of the numpy reference.
// All coefficients become instruction immediates in device code (no LDC).
// ----------------------------------------------------------------------------
struct CD { double re, im; };
constexpr CD cadd(CD a, CD b) { return {a.re + b.re, a.im + b.im}; }
constexpr CD cmulc(CD a, CD b) { return {a.re * b.re - a.im * b.im, a.re * b.im + a.im * b.re}; }
constexpr CD cscale(CD a, double s) { return {a.re * s, a.im * s}; }
constexpr CD cconj(CD a) { return {a.re, -a.im}; }
constexpr bool ciszero(CD a) { return a.re == 0.0 && a.im == 0.0; }

constexpr double cfact(int n) { double r = 1.0; for (int i = 2; i <= n; i++) r *= i; return r; }

constexpr double csqrt_(double x) {
    if (x <= 0.0) return 0.0;
    double y = x > 1.0 ? x : 1.0;
    for (int i = 0; i < 80; i++) {
        double ny = 0.5 * (y + x / y);
        if (ny == y) break;
        y = ny;
    }
    return y;
}

constexpr double su2_cg_c(int j1, int j2, int j3, int m1, int m2, int m3) {
    if (m3 != m1 + m2) return 0.0;
    int vmin = -j1 + j2 + m3;
    if (-j1 + m1 > vmin) vmin = -j1 + m1;
    if (0 > vmin) vmin = 0;
    int vmax = j2 + j3 + m1;
    if (j3 - j1 + j2 < vmax) vmax = j3 - j1 + j2;
    if (j3 + m3 < vmax) vmax = j3 + m3;
    double C = csqrt_((2.0 * j3 + 1.0) * cfact(j3 + j1 - j2) * cfact(j3 - j1 + j2)
                      * cfact(j1 + j2 - j3) * cfact(j3 + m3) * cfact(j3 - m3)
                      / (cfact(j1 + j2 + j3 + 1) * cfact(j1 - m1) * cfact(j1 + m1)
                         * cfact(j2 - m2) * cfact(j2 + m2)));
    double S = 0.0;
    for (int v = vmin; v <= vmax; v++) {
        double sg = ((v + j2 + m2) & 1) ? -1.0 : 1.0;
        S += sg * cfact(j2 + j3 + m1 - v) * cfact(j1 - m1 + v)
             / (cfact(v) * cfact(j3 - j1 + j2 - v) * cfact(j3 + m3 - v)
                * cfact(v + j1 - j2 - m3));
    }
    return C * S;
}

struct QM { CD q[81]; };

constexpr QM change_basis_c(int l) {
    QM Q{};
    int L = 2 * l + 1;
    for (int i = 0; i < L * L; i++) Q.q[i] = CD{0, 0};
    double is2 = 1.0 / csqrt_(2.0);
    for (int m = -l; m < 0; m++) {
        Q.q[(l + m) * L + (l - m)] = CD{is2, 0};
        Q.q[(l + m) * L + (l + m)] = CD{0, -is2};
    }
    Q.q[l * L + l] = CD{1, 0};
    for (int m = 1; m <= l; m++) {
        double sg = (m & 1) ? -1.0 : 1.0;
        Q.q[(l + m) * L + (l + m)] = CD{sg * is2, 0};
        Q.q[(l + m) * L + (l - m)] = CD{0, sg * is2};
    }
    CD ph{1, 0};
    for (int k = 0; k < l; k++) ph = cmulc(ph, CD{0, -1});   // (-i)^l
    for (int i = 0; i < L * L; i++) Q.q[i] = cmulc(Q.q[i], ph);
    return Q;
}

struct W3 { double w[225]; };

constexpr W3 wigner3j_c(int l1, int l2, int l3) {
    int L1 = 2 * l1 + 1, L2 = 2 * l2 + 1, L3 = 2 * l3 + 1;
    QM Q1 = change_basis_c(l1), Q2 = change_basis_c(l2), Q3 = change_basis_c(l3);
    CD acc[225]{};
    for (int t = 0; t < 225; t++) acc[t] = CD{0, 0};
    for (int i = 0; i < L1; i++)
        for (int k = 0; k < L2; k++)
            for (int n = 0; n < L3; n++) {
                double c = su2_cg_c(l1, l2, l3, i - l1, k - l2, n - l3);
                if (c == 0.0) continue;
                for (int j = 0; j < L1; j++) {
                    CD q1 = Q1.q[i * L1 + j];
                    if (ciszero(q1)) continue;
                    for (int l = 0; l < L2; l++) {
                        CD q2 = Q2.q[k * L2 + l];
                        if (ciszero(q2)) continue;
                        CD q12 = cmulc(q1, q2);
                        for (int m = 0; m < L3; m++) {
                            CD q3 = Q3.q[n * L3 + m];
                            if (ciszero(q3)) continue;
                            CD t = cmulc(q12, cconj(q3));
                            int o = (j * L2 + l) * L3 + m;
                            acc[o] = cadd(acc[o], cscale(t, c));
                        }
                    }
                }
            }
    W3 out{};
    double nrm = 0.0;
    for (int t = 0; t < L1 * L2 * L3; t++) { out.w[t] = acc[t].re; nrm += out.w[t] * out.w[t]; }
    nrm = csqrt_(nrm);
    for (int t = 0; t < L1 * L2 * L3; t++) out.w[t] /= nrm;
    return out;
}

struct CGTab { float cg[1225]; float c5[45]; };

constexpr CGTab build_cg_c() {
    CGTab P{};
    const int l1s[9]   = {0, 0, 0, 1, 1, 1, 2, 2, 2};
    const int l2s[9]   = {0, 1, 2, 0, 1, 2, 0, 1, 2};
    const int cgoff[9] = {0, 1, 10, 35, 44, 125, 350, 375, 600};
    for (int p = 0; p < 9; p++) {
        int l1 = l1s[p], l2 = l2s[p];
        int L1 = 2 * l1 + 1, L2 = 2 * l2 + 1, R = L1 * L2;
        int lmin = (l1 > l2) ? (l1 - l2) : (l2 - l1);
        int rof = 0;
        for (int l3 = lmin; l3 <= l1 + l2; l3++) {
            W3 w = wigner3j_c(l1, l2, l3);
            int L3 = 2 * l3 + 1;
            double sc = csqrt_(2.0 * l3 + 1.0);
            for (int a = 0; a < L1; a++)
                for (int b = 0; b < L2; b++)
                    for (int nn = 0; nn < L3; nn++)
                        P.cg[cgoff[p] + (a * L2 + b) * R + rof + nn] =
                            (float)(w.w[(a * L2 + b) * L3 + nn] * sc);
            rof += L3;
        }
    }
    W3 w = wigner3j_c(1, 1, 2);
    double s5 = csqrt_(5.0);
    for (int t = 0; t < 45; t++) P.c5[t] = (float)(w.w[t] * s5);
    return P;
}

constexpr CGTab CGH = build_cg_c();

template <int I> struct CGC { static constexpr float v = CGH.cg[I]; };
template <int I> struct C5C { static constexpr float v = CGH.c5[I]; };

// ----------------------------------------------------------------------------
// Index-sequence machinery
// ----------------------------------------------------------------------------
template <int... Is> struct iseq {};
template <int N, int... Is> struct mkseq_ : mkseq_<N - 1, N - 1, Is...> {};
template <int... Is> struct mkseq_<0, Is...> { using type = iseq<Is...>; };
template <int N> using mkseq = typename mkseq_<N>::type;

template <int IDX>
__device__ __forceinline__ float cgfma(float x, float s) {
    constexpr float c = CGC<IDX>::v;
    if constexpr (c == 0.0f) return s;
    else return fmaf(c, x, s);            // FFMA-imm form, rt=1
}
template <int IDX>
__device__ __forceinline__ float c5fma(float x, float s) {
    constexpr float c = C5C<IDX>::v;
    if constexpr (c == 0.0f) return s;
    else return fmaf(c, x, s);
}

template <int BASE, int... Rs>
__device__ __forceinline__ float cgdot(const float* __restrict__ x, iseq<Rs...>) {
    float s = 0.f;
    ((s = cgfma<BASE + Rs>(x[Rs], s)), ...);
    return s;
}
template <int CGOFF, int R, int... ABs>
__device__ __forceinline__ void cgall(const float* __restrict__ x, float* __restrict__ Hz,
                                      iseq<ABs...>) {
    ((Hz[ABs] = cgdot<CGOFF + ABs * R>(x, mkseq<R>{})), ...);
}

// ----------------------------------------------------------------------------
// Pair transform: CG (immediates) then Dl * Hz * Dr^T, in-place on smem row.
// ----------------------------------------------------------------------------
template <int L1, int L2, int NCH, int CGOFF>
__device__ __forceinline__ void do_pair(float* __restrict__ row,
                                        const float* __restrict__ Dl,
                                        const float* __restrict__ Dr) {
    constexpr int R = L1 * L2;
#pragma unroll
    for (int q = 0; q < NCH; ++q) {
        float x[R];
#pragma unroll
        for (int r = 0; r < R; ++r) x[r] = row[q * R + r];
        float Hz[R];
        cgall<CGOFF, R>(x, Hz, mkseq<R>{});
#pragma unroll
        for (int l = 0; l < L1; ++l) {
            float T[L2];
#pragma unroll
            for (int b = 0; b < L2; ++b) {
                if constexpr (L1 == 1) {
                    T[b] = Hz[b];
                } else {
                    float s = 0.f;
#pragma unroll
                    for (int m = 0; m < L1; ++m)
                        s = fmaf(Dl[l * L1 + m], Hz[m * L2 + b], s);
                    T[b] = s;
                }
            }
#pragma unroll
            for (int k = 0; k < L2; ++k) {
                if constexpr (L2 == 1) {
                    row[q * R + l * L2 + k] = T[0];
                } else {
                    float s = 0.f;
#pragma unroll
                    for (int o = 0; o < L2; ++o)
                        s = fmaf(T[o], Dr[k * L2 + o], s);
                    row[q * R + l * L2 + k] = s;
                }
            }
        }
    }
}

// ----------------------------------------------------------------------------
// D2 = C5^T (D1 (x) D1) C5, all C5 coefficients as immediates.
// ----------------------------------------------------------------------------
template <int N, int N1>
__device__ __forceinline__ float u_ent(const float* __restrict__ d1row) {
    float s = 0.f;
    s = c5fma<(N1 * 3 + 0) * 5 + N>(d1row[0], s);
    s = c5fma<(N1 * 3 + 1) * 5 + N>(d1row[1], s);
    s = c5fma<(N1 * 3 + 2) * 5 + N>(d1row[2], s);
    return s;
}
template <int M, int... MMs>
__device__ __forceinline__ float d2_ent(const float* __restrict__ E, iseq<MMs...>) {
    float s = 0.f;
    ((s = c5fma<MMs * 5 + M>(E[MMs], s)), ...);
    return s;
}
template <int N>
__device__ __forceinline__ void d2_col(const float* __restrict__ D1m, float* __restrict__ D2m) {
    float U[9];
#pragma unroll
    for (int m2 = 0; m2 < 3; ++m2) {
        U[m2 * 3 + 0] = u_ent<N, 0>(D1m + m2 * 3);
        U[m2 * 3 + 1] = u_ent<N, 1>(D1m + m2 * 3);
        U[m2 * 3 + 2] = u_ent<N, 2>(D1m + m2 * 3);
    }
    float E[9];
#pragma unroll
    for (int m1 = 0; m1 < 3; ++m1)
#pragma unroll
        for (int m2 = 0; m2 < 3; ++m2) {
            float s = 0.f;
#pragma unroll
            for (int n1 = 0; n1 < 3; ++n1)
                s = fmaf(D1m[m1 * 3 + n1], U[m2 * 3 + n1], s);
            E[m1 * 3 + m2] = s;
        }
    D2m[0 * 5 + N] = d2_ent<0>(E, mkseq<9>{});
    D2m[1 * 5 + N] = d2_ent<1>(E, mkseq<9>{});
    D2m[2 * 5 + N] = d2_ent<2>(E, mkseq<9>{});
    D2m[3 * 5 + N] = d2_ent<3>(E, mkseq<9>{});
    D2m[4 * 5 + N] = d2_ent<4>(E, mkseq<9>{});
}

// ----------------------------------------------------------------------------
// Kernel: one thread = one edge; two column phases through a half-size tile.
// ----------------------------------------------------------------------------
__global__ void __launch_bounds__(NTHREADS, 4)
e3_kernel(const float* __restrict__ feat, const float* __restrict__ vec,
          float* __restrict__ out, int n) {
    extern __shared__ float tile[];
    const int tid = threadIdx.x;
    const int e0 = blockIdx.x * EPB;
    const int nvalid = min(EPB, n - e0);

    // row base in float4 units: row r of phase A = (e0+r)*49 + 0..23,
    // phase B = (e0+r)*49 + 24..48 (col 96 = float4 index 24).
    const float4* g4 = reinterpret_cast<const float4*>(feat);
    float4* o4 = reinterpret_cast<float4*>(out);

    // ---- D matrices (registers, live across both phases) ----
    float D1m[9], D2m[25];
    if (tid < nvalid) {
        const int e = e0 + tid;
        float vx = vec[3 * e + 0], vy = vec[3 * e + 1], vz = vec[3 * e + 2];
        float inv = rsqrtf(fmaf(vx, vx, fmaf(vy, vy, vz * vz)));
        vx *= inv; vy *= inv; vz *= inv;
        float cb = fminf(1.f, fmaxf(-1.f, vy));
        float sb = sqrtf(fmaxf(0.f, 1.f - cb * cb));
        float rho2 = fmaf(vx, vx, vz * vz);
        float ca, sa;
        if (rho2 > 0.f) {
            float ir = rsqrtf(rho2);
            ca = vz * ir; sa = vx * ir;
        } else { ca = 1.f; sa = 0.f; }
        D1m[0] = ca;   D1m[1] = sa * sb; D1m[2] = sa * cb;
        D1m[3] = 0.f;  D1m[4] = cb;      D1m[5] = -sb;
        D1m[6] = -sa;  D1m[7] = ca * sb; D1m[8] = ca * cb;
        d2_col<0>(D1m, D2m);
        d2_col<1>(D1m, D2m);
        d2_col<2>(D1m, D2m);
        d2_col<3>(D1m, D2m);
        d2_col<4>(D1m, D2m);
    }

    // ================= Phase A: cols [0,96) =================
    {
        const int nA = nvalid * 24;
        for (int i = tid; i < nA; i += NTHREADS) {
            int r = i / 24;
            int c4 = i - r * 24;
            float4 v = g4[(size_t)(e0 + r) * 49 + c4];
            float* p = &tile[r * STRIDE + c4 * 4];
            p[0] = v.x; p[1] = v.y; p[2] = v.z; p[3] = v.w;
        }
        __syncthreads();
        if (tid < nvalid) {
            float* row = &tile[tid * STRIDE];
            do_pair<1, 1, 9, 0  >(row + 0,  D1m, D1m);  // s-s
            do_pair<1, 3, 6, 1  >(row + 9,  D1m, D1m);  // s-p
            do_pair<1, 5, 3, 10 >(row + 27, D1m, D2m);  // s-d
            do_pair<3, 1, 6, 35 >(row + 42, D1m, D1m);  // p-s
            do_pair<3, 3, 4, 44 >(row + 60, D1m, D1m);  // p-p
        }
        __syncthreads();
        for (int i = tid; i < nA; i += NTHREADS) {
            int r = i / 24;
            int c4 = i - r * 24;
            const float* p = &tile[r * STRIDE + c4 * 4];
            o4[(size_t)(e0 + r) * 49 + c4] = make_float4(p[0], p[1], p[2], p[3]);
        }
    }
    __syncthreads();   // tile reads done before phase B overwrites

    // ================= Phase B: cols [96,196) =================
    {
        const int nB = nvalid * 25;
        for (int i = tid; i < nB; i += NTHREADS) {
            int r = i / 25;
            int c4 = i - r * 25;
            float4 v = g4[(size_t)(e0 + r) * 49 + 24 + c4];
            float* p = &tile[r * STRIDE + c4 * 4];
            p[0] = v.x; p[1] = v.y; p[2] = v.z; p[3] = v.w;
        }
        __syncthreads();
        if (tid < nvalid) {
            float* row = &tile[tid * STRIDE];   // col 96 at offset 0
            do_pair<3, 5, 2, 125>(row + 0,  D1m, D2m);  // p-d  (96-96)
            do_pair<5, 1, 3, 350>(row + 30, D2m, D1m);  // d-s  (126-96)
            do_pair<5, 3, 2, 375>(row + 45, D2m, D1m);  // d-p  (141-96)
            do_pair<5, 5, 1, 600>(row + 75, D2m, D2m);  // d-d  (171-96)
        }
        __syncthreads();
        for (int i = tid; i < nB; i += NTHREADS) {
            int r = i / 25;
            int c4 = i - r * 25;
            const float* p = &tile[r * STRIDE + c4 * 4];
            o4[(size_t)(e0 + r) * 49 + 24 + c4] = make_float4(p[0], p[1], p[2], p[3]);
        }
    }
}

// ----------------------------------------------------------------------------
// Launch
// ----------------------------------------------------------------------------
extern "C" void kernel_launch(void* const* d_in, const int* in_sizes, int n_in,
                              void* d_out, int out_size) {
    (void)n_in; (void)out_size;
    const float* feat = (const float*)d_in[0];
    const float* vec  = (const float*)d_in[1];
    float* out = (float*)d_out;
    const int n = in_sizes[0] / NF;

    cudaFuncSetAttribute(e3_kernel, cudaFuncAttributeMaxDynamicSharedMemorySize, SMEM_BYTES);
    int blocks = (n + EPB - 1) / EPB;
    e3_kernel<<<blocks, NTHREADS, SMEM_BYTES>>>(feat, vec, out, n);
}